// round 3
// baseline (speedup 1.0000x reference)
#include <cuda_runtime.h>
#include <math.h>

#define D 128
#define P 17
#define HF 56
#define WF 100
#define BMAX 2
#define WARPS_PER_CTA 4
#define FULLMASK 0xffffffffu

// ---------------- device scratch (no allocations allowed) ----------------
__device__ float g_img[BMAX * HF * WF * D];   // NHWC repack of img_feats
__device__ float g_kWT[D * D];                // kW transposed
__device__ float g_M[D * D];                  // M[a][c] = sum_e qW[a,e] kW[c,e]
__device__ float g_W2[D * D];                 // W2[c][d] = sum_e vW[c,e] outW[e,d]
__device__ float g_mb[D];                     // mb[c] = sum_e qb[e] kW[c,e]
__device__ float g_u[D];                      // u[a]  = sum_e qW[a,e] kb[e]
__device__ float g_vbo[D];                    // vbo[d] = sum_e vb[e] outW[e,d]
__device__ float g_c0;                        // qb . kb

__constant__ float2 c_base[P] = {
    {-1.f,-1.f},{-1.f,0.f},{-1.f,1.f},{0.f,-1.f},{0.f,0.f},{0.f,1.f},
    {1.f,-1.f},{1.f,0.f},{1.f,1.f},{-3.f,-3.f},{-3.f,0.f},{-3.f,3.f},
    {0.f,-3.f},{0.f,3.f},{3.f,-3.f},{3.f,0.f},{3.f,3.f}
};

// ---------------- warp reduce helpers ----------------
__device__ __forceinline__ float wsum(float v) {
    #pragma unroll
    for (int o = 16; o; o >>= 1) v += __shfl_xor_sync(FULLMASK, v, o);
    return v;
}
__device__ __forceinline__ float wmax(float v) {
    #pragma unroll
    for (int o = 16; o; o >>= 1) v = fmaxf(v, __shfl_xor_sync(FULLMASK, v, o));
    return v;
}

// ---------------- prep kernels ----------------
__global__ void prep_img(const float* __restrict__ img, int B) {
    int t = blockIdx.x * blockDim.x + threadIdx.x;
    int total = B * HF * WF * D;
    if (t >= total) return;
    int c = t & (D - 1);
    int r = t >> 7;
    int x = r % WF; r /= WF;
    int y = r % HF;
    int b = r / HF;
    g_img[t] = img[((b * D + c) * HF + y) * WF + x];
}

__global__ void prep_kwt(const float* __restrict__ kW) {
    int t = blockIdx.x * blockDim.x + threadIdx.x;
    if (t >= D * D) return;
    int j = t & (D - 1);
    int e = t >> 7;
    g_kWT[t] = kW[j * D + e];
}

__global__ void prep_M(const float* __restrict__ qW) {
    int a = blockIdx.x, j = threadIdx.x;
    __shared__ float sq[D];
    sq[j] = qW[a * D + j];
    __syncthreads();
    float acc = 0.f;
    #pragma unroll 8
    for (int e = 0; e < D; e++) acc = fmaf(sq[e], g_kWT[e * D + j], acc);
    g_M[a * D + j] = acc;
}

__global__ void prep_W2(const float* __restrict__ vW, const float* __restrict__ outW) {
    int c = blockIdx.x, d = threadIdx.x;
    __shared__ float sv[D];
    sv[d] = vW[c * D + d];
    __syncthreads();
    float acc = 0.f;
    #pragma unroll 8
    for (int e = 0; e < D; e++) acc = fmaf(sv[e], outW[e * D + d], acc);
    g_W2[c * D + d] = acc;
}

__global__ void prep_vec(const float* __restrict__ qW, const float* __restrict__ kW,
                         const float* __restrict__ qb, const float* __restrict__ kb,
                         const float* __restrict__ vb, const float* __restrict__ outW) {
    int i = threadIdx.x;
    float mb = 0.f, u = 0.f, vo = 0.f;
    for (int e = 0; e < D; e++) {
        mb = fmaf(qb[e], kW[i * D + e], mb);
        u  = fmaf(qW[i * D + e], kb[e], u);
        vo = fmaf(vb[e], outW[e * D + i], vo);
    }
    g_mb[i] = mb; g_u[i] = u; g_vbo[i] = vo;
    if (i == 0) {
        float c = 0.f;
        for (int e = 0; e < D; e++) c = fmaf(qb[e], kb[e], c);
        g_c0 = c;
    }
}

// ---------------- main fused kernel: one warp per voxel ----------------
__global__ void __launch_bounds__(WARPS_PER_CTA * 32)
fusion_main(const float* __restrict__ x_lidar, const int* __restrict__ indices,
            const float* __restrict__ voxel_size, const float* __restrict__ pc_range,
            const float* __restrict__ trans,
            const float* __restrict__ offW, const float* __restrict__ offb,
            const float* __restrict__ outb,
            const int* __restrict__ Himg, const int* __restrict__ Wimg,
            float* __restrict__ out, int N) {
    const int warp = threadIdx.x >> 5;
    const int lane = threadIdx.x & 31;
    const int n = blockIdx.x * WARPS_PER_CTA + warp;
    if (n >= N) return;

    __shared__ float sx[WARPS_PER_CTA][D];
    __shared__ float ssamp[WARPS_PER_CTA][P][D];
    __shared__ float sagg[WARPS_PER_CTA][D];

    // stage x row into smem (and keep float4 in regs for the u-dot)
    float4 xv = *(const float4*)&x_lidar[(size_t)n * D + 4 * lane];
    *(float4*)&sx[warp][4 * lane] = xv;
    __syncwarp();

    // ---- projection of voxel center to feature-map normalized coords ----
    int4 vidx = *(const int4*)&indices[(size_t)n * 4];
    int b = vidx.x;
    float cv0 = voxel_size[0] * 8.0f, cv1 = voxel_size[1] * 8.0f, cv2 = voxel_size[2] * 8.0f;
    float ph0 = (float)vidx.w * cv0 + pc_range[0] + cv0 * 0.5f;
    float ph1 = (float)vidx.z * cv1 + pc_range[1] + cv1 * 0.5f;
    float ph2 = (float)vidx.y * cv2 + pc_range[2] + cv2 * 0.5f;
    const float* T = trans + b * 12;
    float X = T[0]*ph0 + T[1]*ph1 + T[2]*ph2 + T[3];
    float Y = T[4]*ph0 + T[5]*ph1 + T[6]*ph2 + T[7];
    float Z = T[8]*ph0 + T[9]*ph1 + T[10]*ph2 + T[11];
    float depth = fmaxf(Z, 1e-5f);
    float uf = X / depth * ((float)WF / (float)Wimg[0]);
    float vf = Y / depth * ((float)HF / (float)Himg[0]);
    float un = 2.0f * (uf / (float)(WF - 1)) - 1.0f;
    float vn = 2.0f * (vf / (float)(HF - 1)) - 1.0f;
    const float du = 2.0f / (float)(WF - 1);
    const float dv = 2.0f / (float)(HF - 1);

    // ---- learned offsets: lane p < 17 computes its point's (dx, dy) ----
    float gx = 0.f, gy = 0.f, lnorm = 0.f;
    bool myvalid = false;
    if (lane < P) {
        float ax = 0.f, ay = 0.f;
        const float2* ow2 = (const float2*)offW;   // row c = 17 float2, 8B-aligned
        #pragma unroll 4
        for (int c = 0; c < D; c++) {
            float xc = sx[warp][c];
            float2 w = ow2[c * P + lane];
            ax = fmaf(xc, w.x, ax);
            ay = fmaf(xc, w.y, ay);
        }
        float2 ob = ((const float2*)offb)[lane];
        float dx = tanhf(ax + ob.x) * (1.5f * du);
        float dy = tanhf(ay + ob.y) * (1.5f * dv);
        gx = un + c_base[lane].x * du + dx;
        gy = vn + c_base[lane].y * dv + dy;
        myvalid = (fabsf(gx) <= 1.0f) && (fabsf(gy) <= 1.0f);
        lnorm = sqrtf(dx * dx + dy * dy);
    }
    unsigned vm = __ballot_sync(FULLMASK, myvalid);

    // ---- qdotkb = x . u + c0 (q . k_b folded) ----
    float4 u4 = *(const float4*)&g_u[4 * lane];
    float pq = xv.x*u4.x + xv.y*u4.y + xv.z*u4.z + xv.w*u4.w;
    float qdotkb = wsum(pq) + g_c0;

    // ---- qk[c] = x @ M + mb ; lane holds channels 4*lane..4*lane+3 ----
    float4 qk = make_float4(0.f, 0.f, 0.f, 0.f);
    #pragma unroll 4
    for (int a = 0; a < D; a++) {
        float xa = sx[warp][a];
        float4 m = *(const float4*)&g_M[a * D + 4 * lane];
        qk.x = fmaf(xa, m.x, qk.x); qk.y = fmaf(xa, m.y, qk.y);
        qk.z = fmaf(xa, m.z, qk.z); qk.w = fmaf(xa, m.w, qk.w);
    }
    {
        float4 mb4 = *(const float4*)&g_mb[4 * lane];
        qk.x += mb4.x; qk.y += mb4.y; qk.z += mb4.z; qk.w += mb4.w;
    }

    const float scale = 1.0f / sqrtf(32.0f);   // (D/NUM_HEADS)^-0.5

    // ---- gather (bilinear, NHWC) + attention logits ----
    float myattn = -3.0e38f;
    const float* ib = g_img + (size_t)b * HF * WF * D;
    for (int p = 0; p < P; p++) {
        bool pv = (vm >> p) & 1u;     // warp-uniform
        if (!pv) {
            if (lane == p) myattn = -10000.0f;
            continue;
        }
        float gxp = __shfl_sync(FULLMASK, gx, p);
        float gyp = __shfl_sync(FULLMASK, gy, p);
        float px = (gxp + 1.0f) * 0.5f * (float)(WF - 1);
        float py = (gyp + 1.0f) * 0.5f * (float)(HF - 1);
        float fx0 = floorf(px), fy0 = floorf(py);
        int ix = (int)fx0, iy = (int)fy0;
        float fx = px - fx0, fy = py - fy0;
        float4 acc = make_float4(0.f, 0.f, 0.f, 0.f);
        #pragma unroll
        for (int t = 0; t < 4; t++) {
            int dxt = t & 1, dyt = t >> 1;
            int xc = ix + dxt, yc = iy + dyt;
            if (xc >= 0 && xc < WF && yc >= 0 && yc < HF) {
                float w = (dxt ? fx : 1.0f - fx) * (dyt ? fy : 1.0f - fy);
                float4 v = *(const float4*)&ib[(yc * WF + xc) * D + 4 * lane];
                acc.x = fmaf(w, v.x, acc.x); acc.y = fmaf(w, v.y, acc.y);
                acc.z = fmaf(w, v.z, acc.z); acc.w = fmaf(w, v.w, acc.w);
            }
        }
        *(float4*)&ssamp[warp][p][4 * lane] = acc;
        float pd = acc.x*qk.x + acc.y*qk.y + acc.z*qk.z + acc.w*qk.w;
        pd = wsum(pd);
        float a = (pd + qdotkb) * scale;
        if (lane == p) myattn = a;
    }
    __syncwarp();

    // ---- softmax with mask + renormalization ----
    float m = wmax(lane < P ? myattn : -3.0e38f);
    float e = (lane < P) ? expf(myattn - m) : 0.f;
    float s1 = wsum(e);
    float psm = e / s1;
    float w = myvalid ? psm : 0.f;
    float s2 = wsum(w);
    float wn = w / fmaxf(s2, 1e-6f);
    float s_n = s2 / fmaxf(s2, 1e-6f);

    // ---- weighted aggregation of sampled features ----
    float4 agg = make_float4(0.f, 0.f, 0.f, 0.f);
    for (int p = 0; p < P; p++) {
        float wp = __shfl_sync(FULLMASK, wn, p);
        if (wp != 0.f) {
            float4 sv = *(const float4*)&ssamp[warp][p][4 * lane];
            agg.x = fmaf(wp, sv.x, agg.x); agg.y = fmaf(wp, sv.y, agg.y);
            agg.z = fmaf(wp, sv.z, agg.z); agg.w = fmaf(wp, sv.w, agg.w);
        }
    }
    *(float4*)&sagg[warp][4 * lane] = agg;
    __syncwarp();

    // ---- final fused (v_W @ out_W) GEMV + biases ----
    float4 vbo = *(const float4*)&g_vbo[4 * lane];
    float4 ob4 = *(const float4*)&outb[4 * lane];
    float4 o;
    o.x = fmaf(s_n, vbo.x, ob4.x); o.y = fmaf(s_n, vbo.y, ob4.y);
    o.z = fmaf(s_n, vbo.z, ob4.z); o.w = fmaf(s_n, vbo.w, ob4.w);
    #pragma unroll 4
    for (int c = 0; c < D; c++) {
        float ac = sagg[warp][c];
        float4 w2 = *(const float4*)&g_W2[c * D + 4 * lane];
        o.x = fmaf(ac, w2.x, o.x); o.y = fmaf(ac, w2.y, o.y);
        o.z = fmaf(ac, w2.z, o.z); o.w = fmaf(ac, w2.w, o.w);
    }
    *(float4*)&out[(size_t)n * D + 4 * lane] = o;

    // ---- stats ----
    float vcnt = wsum((lane < P && myvalid) ? 1.0f : 0.f);
    float lsum = wsum(lane < P ? lnorm : 0.f);
    float pe = fmaxf(wn, 1e-6f);
    float ent = wsum(lane < P ? (-pe * logf(pe)) : 0.f);
    if (lane == 0) {
        size_t base = (size_t)N * D;
        out[base + n] = vcnt / 17.0f;
        float oscale = 1.5f * fmaxf(sqrtf(du * du + dv * dv), 1e-6f);
        float instab = (lsum / 17.0f) / oscale;
        out[base + N + n]     = fminf(fmaxf(expf(-instab), 0.f), 1.f);
        float focus = 1.0f - ent / logf(17.0f);
        out[base + 2 * (size_t)N + n] = fminf(fmaxf(focus, 0.f), 1.f);
    }
}

// ---------------- launch ----------------
extern "C" void kernel_launch(void* const* d_in, const int* in_sizes, int n_in,
                              void* d_out, int out_size) {
    const float* x_lidar = (const float*)d_in[0];
    const int*   indices = (const int*)d_in[1];
    const float* img     = (const float*)d_in[2];
    const float* vsize   = (const float*)d_in[3];
    const float* pcr     = (const float*)d_in[4];
    const float* trans   = (const float*)d_in[5];
    const float* offW    = (const float*)d_in[6];
    const float* offb    = (const float*)d_in[7];
    const float* qW      = (const float*)d_in[8];
    const float* qb      = (const float*)d_in[9];
    const float* kW      = (const float*)d_in[10];
    const float* kb      = (const float*)d_in[11];
    const float* vW      = (const float*)d_in[12];
    const float* vb      = (const float*)d_in[13];
    const float* outW    = (const float*)d_in[14];
    const float* outb    = (const float*)d_in[15];
    const int*   Himg    = (const int*)d_in[16];
    const int*   Wimg    = (const int*)d_in[17];

    int N = in_sizes[0] / D;
    int B = in_sizes[5] / 12;
    if (B > BMAX) B = BMAX;

    int imgTotal = B * HF * WF * D;
    prep_img<<<(imgTotal + 255) / 256, 256>>>(img, B);
    prep_kwt<<<(D * D + 255) / 256, 256>>>(kW);
    prep_M<<<D, D>>>(qW);
    prep_W2<<<D, D>>>(vW, outW);
    prep_vec<<<1, D>>>(qW, kW, qb, kb, vb, outW);

    int blocks = (N + WARPS_PER_CTA - 1) / WARPS_PER_CTA;
    fusion_main<<<blocks, WARPS_PER_CTA * 32>>>(
        x_lidar, indices, vsize, pcr, trans, offW, offb, outb,
        Himg, Wimg, (float*)d_out, N);
}

// round 5
// speedup vs baseline: 1.9465x; 1.9465x over previous
#include <cuda_runtime.h>
#include <math.h>

#define D 128
#define P 17
#define HF 56
#define WF 100
#define BMAX 2
#define VPW 4                      // voxels per warp
#define WARPS_PER_CTA 4
#define FULLMASK 0xffffffffu

// ---------------- device scratch (no allocations allowed) ----------------
__device__ float g_img[BMAX * HF * WF * D];   // NHWC repack of img_feats
__device__ float g_kWT[D * D];
__device__ float g_M[D * D];                  // qW @ kW^T
__device__ float g_W2[D * D];                 // vW @ outW
__device__ float g_mb[D];                     // qb @ kW^T
__device__ float g_u[D];                      // qW @ kb
__device__ float g_vbo[D];                    // vb @ outW
__device__ float g_c0;                        // qb . kb

__constant__ float2 c_base[P] = {
    {-1.f,-1.f},{-1.f,0.f},{-1.f,1.f},{0.f,-1.f},{0.f,0.f},{0.f,1.f},
    {1.f,-1.f},{1.f,0.f},{1.f,1.f},{-3.f,-3.f},{-3.f,0.f},{-3.f,3.f},
    {0.f,-3.f},{0.f,3.f},{3.f,-3.f},{3.f,0.f},{3.f,3.f}
};

__device__ __forceinline__ float wsum(float v) {
    #pragma unroll
    for (int o = 16; o; o >>= 1) v += __shfl_xor_sync(FULLMASK, v, o);
    return v;
}

// ---------------- prep kernels ----------------
__global__ void prep_img(const float* __restrict__ img, int B) {
    int t = blockIdx.x * blockDim.x + threadIdx.x;
    int total = B * HF * WF * D;
    if (t >= total) return;
    int c = t & (D - 1);
    int r = t >> 7;
    int x = r % WF; r /= WF;
    int y = r % HF;
    int b = r / HF;
    g_img[t] = img[((b * D + c) * HF + y) * WF + x];
}

__global__ void prep_kwt(const float* __restrict__ kW) {
    int t = blockIdx.x * blockDim.x + threadIdx.x;
    if (t >= D * D) return;
    int j = t & (D - 1);
    int e = t >> 7;
    g_kWT[t] = kW[j * D + e];
}

__global__ void prep_M(const float* __restrict__ qW) {
    int a = blockIdx.x, j = threadIdx.x;
    __shared__ float sq[D];
    sq[j] = qW[a * D + j];
    __syncthreads();
    float acc = 0.f;
    #pragma unroll 8
    for (int e = 0; e < D; e++) acc = fmaf(sq[e], g_kWT[e * D + j], acc);
    g_M[a * D + j] = acc;
}

__global__ void prep_W2(const float* __restrict__ vW, const float* __restrict__ outW) {
    int c = blockIdx.x, d = threadIdx.x;
    __shared__ float sv[D];
    sv[d] = vW[c * D + d];
    __syncthreads();
    float acc = 0.f;
    #pragma unroll 8
    for (int e = 0; e < D; e++) acc = fmaf(sv[e], outW[e * D + d], acc);
    g_W2[c * D + d] = acc;
}

__global__ void prep_vec(const float* __restrict__ qW, const float* __restrict__ kW,
                         const float* __restrict__ qb, const float* __restrict__ kb,
                         const float* __restrict__ vb, const float* __restrict__ outW) {
    int i = threadIdx.x;
    float mb = 0.f, u = 0.f, vo = 0.f;
    for (int e = 0; e < D; e++) {
        mb = fmaf(qb[e], kW[i * D + e], mb);
        u  = fmaf(qW[i * D + e], kb[e], u);
        vo = fmaf(vb[e], outW[e * D + i], vo);
    }
    g_mb[i] = mb; g_u[i] = u; g_vbo[i] = vo;
    if (i == 0) {
        float c = 0.f;
        for (int e = 0; e < D; e++) c = fmaf(qb[e], kb[e], c);
        g_c0 = c;
    }
}

// ---------------- main fused kernel: 4 voxels per warp ----------------
__global__ void __launch_bounds__(WARPS_PER_CTA * 32)
fusion_main(const float* __restrict__ x_lidar, const int* __restrict__ indices,
            const float* __restrict__ voxel_size, const float* __restrict__ pc_range,
            const float* __restrict__ trans,
            const float* __restrict__ offW, const float* __restrict__ offb,
            const float* __restrict__ outb,
            const int* __restrict__ Himg, const int* __restrict__ Wimg,
            float* __restrict__ out, int N) {
    const int warp = threadIdx.x >> 5;
    const int lane = threadIdx.x & 31;
    const int n0 = (blockIdx.x * WARPS_PER_CTA + warp) * VPW;
    if (n0 >= N) return;

    __shared__ float sx[WARPS_PER_CTA][VPW][D];     // x rows
    __shared__ float sagg[WARPS_PER_CTA][VPW][D];   // normalized aggregates

    const float du = 2.0f / (float)(WF - 1);
    const float dv = 2.0f / (float)(HF - 1);
    const float scale = 0.1767766953f;               // 32^-0.5

    // hoisted warp-uniform scalars
    float cv0 = voxel_size[0] * 8.0f, cv1 = voxel_size[1] * 8.0f, cv2 = voxel_size[2] * 8.0f;
    float pr0 = pc_range[0], pr1 = pc_range[1], pr2 = pc_range[2];
    float wsc = (float)WF / (float)Wimg[0];
    float hsc = (float)HF / (float)Himg[0];

    int   bv[VPW];
    float unv[VPW], vnv[VPW];

    #pragma unroll
    for (int v = 0; v < VPW; v++) {
        int n = n0 + v; if (n >= N) n = N - 1;
        float4 xr = *(const float4*)&x_lidar[(size_t)n * D + 4 * lane];
        *(float4*)&sx[warp][v][4 * lane] = xr;

        int4 vidx = *(const int4*)&indices[(size_t)n * 4];
        bv[v] = vidx.x;
        float ph0 = (float)vidx.w * cv0 + pr0 + cv0 * 0.5f;
        float ph1 = (float)vidx.z * cv1 + pr1 + cv1 * 0.5f;
        float ph2 = (float)vidx.y * cv2 + pr2 + cv2 * 0.5f;
        const float* T = trans + bv[v] * 12;
        float X = T[0]*ph0 + T[1]*ph1 + T[2]*ph2 + T[3];
        float Y = T[4]*ph0 + T[5]*ph1 + T[6]*ph2 + T[7];
        float Z = T[8]*ph0 + T[9]*ph1 + T[10]*ph2 + T[11];
        float depth = fmaxf(Z, 1e-5f);
        unv[v] = 2.0f * ((X / depth * wsc) / (float)(WF - 1)) - 1.0f;
        vnv[v] = 2.0f * ((Y / depth * hsc) / (float)(HF - 1)) - 1.0f;
    }
    __syncwarp();

    // ---- learned offsets (lanes < 17), all 4 voxels per weight load ----
    float ax[VPW] = {0.f,0.f,0.f,0.f}, ay[VPW] = {0.f,0.f,0.f,0.f};
    if (lane < P) {
        const float2* ow2 = (const float2*)offW;
        #pragma unroll 4
        for (int c = 0; c < D; c++) {
            float2 w = ow2[c * P + lane];
            #pragma unroll
            for (int v = 0; v < VPW; v++) {
                float xc = sx[warp][v][c];
                ax[v] = fmaf(xc, w.x, ax[v]);
                ay[v] = fmaf(xc, w.y, ay[v]);
            }
        }
    }
    float gx[VPW], gy[VPW], ln[VPW];
    unsigned vm[VPW];
    {
        float2 ob = (lane < P) ? ((const float2*)offb)[lane] : make_float2(0.f, 0.f);
        float bx = (lane < P) ? c_base[lane].x : 0.f;
        float by = (lane < P) ? c_base[lane].y : 0.f;
        #pragma unroll
        for (int v = 0; v < VPW; v++) {
            float dx = tanhf(ax[v] + ob.x) * (1.5f * du);
            float dy = tanhf(ay[v] + ob.y) * (1.5f * dv);
            gx[v] = unv[v] + bx * du + dx;
            gy[v] = vnv[v] + by * dv + dy;
            ln[v] = sqrtf(dx * dx + dy * dy);
            bool val = (lane < P) && (fabsf(gx[v]) <= 1.0f) && (fabsf(gy[v]) <= 1.0f);
            vm[v] = __ballot_sync(FULLMASK, val);
        }
    }

    // ---- q . k_b per voxel ----
    float4 u4 = *(const float4*)&g_u[4 * lane];
    float c0 = g_c0;
    float qdk[VPW];
    #pragma unroll
    for (int v = 0; v < VPW; v++) {
        float4 xr = *(const float4*)&sx[warp][v][4 * lane];
        qdk[v] = wsum(xr.x*u4.x + xr.y*u4.y + xr.z*u4.z + xr.w*u4.w) + c0;
    }

    // ---- qk = x @ M + mb, 4 voxels per M load ----
    float4 qk[VPW];
    #pragma unroll
    for (int v = 0; v < VPW; v++) qk[v] = make_float4(0.f,0.f,0.f,0.f);
    #pragma unroll 4
    for (int a = 0; a < D; a++) {
        float4 m = *(const float4*)&g_M[a * D + 4 * lane];
        #pragma unroll
        for (int v = 0; v < VPW; v++) {
            float xa = sx[warp][v][a];
            qk[v].x = fmaf(xa, m.x, qk[v].x); qk[v].y = fmaf(xa, m.y, qk[v].y);
            qk[v].z = fmaf(xa, m.z, qk[v].z); qk[v].w = fmaf(xa, m.w, qk[v].w);
        }
    }
    {
        float4 mb4 = *(const float4*)&g_mb[4 * lane];
        #pragma unroll
        for (int v = 0; v < VPW; v++) {
            qk[v].x += mb4.x; qk[v].y += mb4.y; qk[v].z += mb4.z; qk[v].w += mb4.w;
        }
    }

    // ---- per-voxel gather + online softmax + stats ----
    float s_n[VPW];
    #pragma unroll
    for (int v = 0; v < VPW; v++) {
        const float* ib = g_img + (size_t)bv[v] * (HF * WF * D);
        float m_run = -3.0e38f, ssum = 0.f;
        float4 agg = make_float4(0.f,0.f,0.f,0.f);
        float myattn = 0.f;

        for (int p = 0; p < P; p++) {
            if (!((vm[v] >> p) & 1u)) continue;     // warp-uniform
            float gxp = __shfl_sync(FULLMASK, gx[v], p);
            float gyp = __shfl_sync(FULLMASK, gy[v], p);
            float px = (gxp + 1.0f) * 0.5f * (float)(WF - 1);
            float py = (gyp + 1.0f) * 0.5f * (float)(HF - 1);
            float fx0 = floorf(px), fy0 = floorf(py);
            int ix = (int)fx0, iy = (int)fy0;
            float fx = px - fx0, fy = py - fy0;
            float4 feat = make_float4(0.f,0.f,0.f,0.f);
            #pragma unroll
            for (int t = 0; t < 4; t++) {
                int dxt = t & 1, dyt = t >> 1;
                int xc = ix + dxt, yc = iy + dyt;
                if (xc >= 0 && xc < WF && yc >= 0 && yc < HF) {
                    float w = (dxt ? fx : 1.0f - fx) * (dyt ? fy : 1.0f - fy);
                    float4 f = *(const float4*)&ib[(yc * WF + xc) * D + 4 * lane];
                    feat.x = fmaf(w, f.x, feat.x); feat.y = fmaf(w, f.y, feat.y);
                    feat.z = fmaf(w, f.z, feat.z); feat.w = fmaf(w, f.w, feat.w);
                }
            }
            float pd = feat.x*qk[v].x + feat.y*qk[v].y + feat.z*qk[v].z + feat.w*qk[v].w;
            float a = (wsum(pd) + qdk[v]) * scale;
            float nm = fmaxf(m_run, a);
            float cc = expf(m_run - nm);
            float e  = expf(a - nm);
            ssum = ssum * cc + e;
            agg.x = agg.x * cc + e * feat.x; agg.y = agg.y * cc + e * feat.y;
            agg.z = agg.z * cc + e * feat.z; agg.w = agg.w * cc + e * feat.w;
            m_run = nm;
            if (lane == p) myattn = a;
        }

        bool anyv = (vm[v] != 0u);
        float inv_s = anyv ? (1.0f / ssum) : 0.f;
        s_n[v] = anyv ? 1.0f : 0.f;
        float4 an = make_float4(agg.x*inv_s, agg.y*inv_s, agg.z*inv_s, agg.w*inv_s);
        *(float4*)&sagg[warp][v][4 * lane] = an;

        // stats (wn reconstructed from stored logit)
        float wn = (lane < P && ((vm[v] >> lane) & 1u)) ? expf(myattn - m_run) * inv_s : 0.f;
        float pe = fmaxf(wn, 1e-6f);
        float ent  = wsum(lane < P ? (-pe * logf(pe)) : 0.f);
        float lsum = wsum(lane < P ? ln[v] : 0.f);
        int n = n0 + v;
        if (lane == 0 && n < N) {
            size_t base = (size_t)N * D;
            out[base + n] = (float)__popc(vm[v]) / 17.0f;
            float oscale = 1.5f * fmaxf(sqrtf(du*du + dv*dv), 1e-6f);
            float instab = (lsum / 17.0f) / oscale;
            out[base + N + n] = fminf(fmaxf(expf(-instab), 0.f), 1.f);
            float focus = 1.0f - ent / logf(17.0f);
            out[base + 2 * (size_t)N + n] = fminf(fmaxf(focus, 0.f), 1.f);
        }
    }
    __syncwarp();

    // ---- out = agg @ W2 + s_n*vbo + outb, 4 voxels per W2 load ----
    float4 vbo = *(const float4*)&g_vbo[4 * lane];
    float4 ob4 = *(const float4*)&outb[4 * lane];
    float4 o[VPW];
    #pragma unroll
    for (int v = 0; v < VPW; v++) {
        o[v].x = fmaf(s_n[v], vbo.x, ob4.x); o[v].y = fmaf(s_n[v], vbo.y, ob4.y);
        o[v].z = fmaf(s_n[v], vbo.z, ob4.z); o[v].w = fmaf(s_n[v], vbo.w, ob4.w);
    }
    #pragma unroll 4
    for (int c = 0; c < D; c++) {
        float4 w2 = *(const float4*)&g_W2[c * D + 4 * lane];
        #pragma unroll
        for (int v = 0; v < VPW; v++) {
            float ac = sagg[warp][v][c];
            o[v].x = fmaf(ac, w2.x, o[v].x); o[v].y = fmaf(ac, w2.y, o[v].y);
            o[v].z = fmaf(ac, w2.z, o[v].z); o[v].w = fmaf(ac, w2.w, o[v].w);
        }
    }
    #pragma unroll
    for (int v = 0; v < VPW; v++) {
        int n = n0 + v;
        if (n < N) *(float4*)&out[(size_t)n * D + 4 * lane] = o[v];
    }
}

// ---------------- launch ----------------
extern "C" void kernel_launch(void* const* d_in, const int* in_sizes, int n_in,
                              void* d_out, int out_size) {
    const float* x_lidar = (const float*)d_in[0];
    const int*   indices = (const int*)d_in[1];
    const float* img     = (const float*)d_in[2];
    const float* vsize   = (const float*)d_in[3];
    const float* pcr     = (const float*)d_in[4];
    const float* trans   = (const float*)d_in[5];
    const float* offW    = (const float*)d_in[6];
    const float* offb    = (const float*)d_in[7];
    const float* qW      = (const float*)d_in[8];
    const float* qb      = (const float*)d_in[9];
    const float* kW      = (const float*)d_in[10];
    const float* kb      = (const float*)d_in[11];
    const float* vW      = (const float*)d_in[12];
    const float* vb      = (const float*)d_in[13];
    const float* outW    = (const float*)d_in[14];
    const float* outb    = (const float*)d_in[15];
    const int*   Himg    = (const int*)d_in[16];
    const int*   Wimg    = (const int*)d_in[17];

    int N = in_sizes[0] / D;
    int B = in_sizes[5] / 12;
    if (B > BMAX) B = BMAX;

    int imgTotal = B * HF * WF * D;
    prep_img<<<(imgTotal + 255) / 256, 256>>>(img, B);
    prep_kwt<<<(D * D + 255) / 256, 256>>>(kW);
    prep_M<<<D, D>>>(qW);
    prep_W2<<<D, D>>>(vW, outW);
    prep_vec<<<1, D>>>(qW, kW, qb, kb, vb, outW);

    int voxPerCta = WARPS_PER_CTA * VPW;
    int blocks = (N + voxPerCta - 1) / voxPerCta;
    fusion_main<<<blocks, WARPS_PER_CTA * 32>>>(
        x_lidar, indices, vsize, pcr, trans, offW, offb, outb,
        Himg, Wimg, (float*)d_out, N);
}